// round 12
// baseline (speedup 1.0000x reference)
#include <cuda_runtime.h>
#include <cuda_fp16.h>
#include <cstdint>

// ============================================================================
// Soft-quantization codebook kernel — ldmatrix + mma.sync HMMA path.
//
// R11 -> R12: the global pre-sort was correct but its scatter used contended
// global atomics (43us!). Replaced with a contention-free counting-sort pass:
//   k_hist:   per-block smem histogram -> plain stores g_cnt[bin][block]
//   k_scan:   hierarchical exclusive prefix -> g_ofs[bin][block]
//   k_scatter: rank = g_ofs + smem-local offset (no global atomics)
// Main kernel identical to R11 (16 warps/SM, +-32 window, ~5-step unions).
// ============================================================================

#define ROWSMAX  262144
#define KANCH    256
#define EDIM     64
#define B_STRIDE 144                // bytes per B k-row: 72 f16 (64 E + ones col + zeros)
#define WRAD     32                 // window radius in anchors
#define SBLK     1024               // sort block size
#define NBLKMAX  512

__device__ int   g_cnt[KANCH * NBLKMAX];
__device__ int   g_ofs[KANCH * NBLKMAX];
__device__ float g_sortedX[ROWSMAX];
__device__ int   g_sortedIdx[ROWSMAX];

__device__ __forceinline__ uint32_t smem_u32(const void* p) {
    uint32_t a;
    asm("{ .reg .u64 t; cvta.to.shared.u64 t, %1; cvt.u32.u64 %0, t; }" : "=r"(a) : "l"(p));
    return a;
}

__device__ __forceinline__ float ex2f(float x) {
    float r;
    asm("ex2.approx.ftz.f32 %0, %1;" : "=f"(r) : "f"(x));
    return r;
}

__device__ __forceinline__ int anchor_bin(float xv, float A0, float rdlt) {
    int i0 = __float2int_rn((xv - A0) * rdlt);
    return min(max(i0, 0), KANCH - 1);
}

#define LDMATRIX_X4T(r0, r1, r2, r3, addr)                                        \
    asm volatile("ldmatrix.sync.aligned.m8n8.x4.trans.shared.b16 {%0,%1,%2,%3}, [%4];" \
        : "=r"(r0), "=r"(r1), "=r"(r2), "=r"(r3) : "r"(addr))

#define LDMATRIX_X2T(r0, r1, addr)                                                \
    asm volatile("ldmatrix.sync.aligned.m8n8.x2.trans.shared.b16 {%0,%1}, [%2];"  \
        : "=r"(r0), "=r"(r1) : "r"(addr))

#define MMA16816(c, a, b)                                                         \
    asm volatile("mma.sync.aligned.m16n8k16.row.col.f32.f16.f16.f32 "             \
        "{%0,%1,%2,%3}, {%4,%5,%6,%7}, {%8,%9}, {%0,%1,%2,%3};"                   \
        : "+f"((c)[0]), "+f"((c)[1]), "+f"((c)[2]), "+f"((c)[3])                  \
        : "r"((a)[0]), "r"((a)[1]), "r"((a)[2]), "r"((a)[3]),                     \
          "r"((b)[0]), "r"((b)[1]))

#define CVT_F16X2(d, hi, lo) \
    asm("cvt.rn.f16x2.f32 %0, %1, %2;" : "=r"(d) : "f"(hi), "f"(lo))

// ---------------- sort pipeline (contention-free) ----------------

__global__ void __launch_bounds__(SBLK)
k_hist(const float* __restrict__ xg, const float* __restrict__ anchors_g,
       int n, int nblk) {
    __shared__ int sh[KANCH];
    const int tid = threadIdx.x;
    if (tid < KANCH) sh[tid] = 0;
    __syncthreads();
    const int i = blockIdx.x * SBLK + tid;
    const float A0 = anchors_g[0];
    const float rdlt = 1.0f / (anchors_g[1] - anchors_g[0]);
    if (i < n) atomicAdd(&sh[anchor_bin(xg[i], A0, rdlt)], 1);
    __syncthreads();
    if (tid < KANCH) g_cnt[tid * nblk + blockIdx.x] = sh[tid];   // plain store
}

__global__ void __launch_bounds__(KANCH)
k_scan(int nblk) {
    __shared__ int sTot[KANCH];
    const int t = threadIdx.x;          // t = bin
    int run = 0;
    for (int blk = 0; blk < nblk; blk++) {
        const int c = g_cnt[t * nblk + blk];
        g_ofs[t * nblk + blk] = run;
        run += c;
    }
    sTot[t] = run;
    __syncthreads();
    // Hillis-Steele inclusive scan -> exclusive base
    int v = run;
    #pragma unroll
    for (int off = 1; off < KANCH; off <<= 1) {
        const int u = (t >= off) ? sTot[t - off] : 0;
        __syncthreads();
        sTot[t] = v = v + u;
        __syncthreads();
    }
    const int base = sTot[t] - run;     // exclusive prefix of bin totals
    for (int blk = 0; blk < nblk; blk++)
        g_ofs[t * nblk + blk] += base;
}

__global__ void __launch_bounds__(SBLK)
k_scatter(const float* __restrict__ xg, const float* __restrict__ anchors_g,
          int n, int nblk) {
    __shared__ int sh[KANCH];
    const int tid = threadIdx.x;
    if (tid < KANCH) sh[tid] = 0;
    __syncthreads();
    const int i = blockIdx.x * SBLK + tid;
    if (i >= n) return;
    const float A0 = anchors_g[0];
    const float rdlt = 1.0f / (anchors_g[1] - anchors_g[0]);
    const float xv = xg[i];
    const int bin = anchor_bin(xv, A0, rdlt);
    const int localOff = atomicAdd(&sh[bin], 1);        // smem-local, low contention
    const int pos = g_ofs[bin * nblk + blockIdx.x] + localOff;
    g_sortedX[pos]   = xv;
    g_sortedIdx[pos] = i;
}

// ---------------- main kernel (identical to R11) ----------------

__global__ void __launch_bounds__(128, 4)
softquant_kernel(const float* __restrict__ anchors_g,
                 const float* __restrict__ emb_g,
                 const float* __restrict__ gamma_g,
                 float* __restrict__ out_g,
                 int ntiles)                      // tiles of 64 rows
{
    __shared__ __align__(128) unsigned char sBmem[KANCH * B_STRIDE];  // 36864 B
    __shared__ float sAnch[KANCH];

    const uint32_t smB = smem_u32(sBmem);

    const int tid   = threadIdx.x;
    const int lane  = tid & 31;
    const int warp  = tid >> 5;
    const int group = lane >> 2;     // 0..7
    const int q     = lane & 3;      // k-slot quad index

    // ---- one-time per CTA: E f32 -> f16 smem B cols 0..63 ----
    #pragma unroll
    for (int i = 0; i < 32; i++) {
        const int idx4 = tid + i * 128;
        const float4 v = reinterpret_cast<const float4*>(emb_g)[idx4];
        const int base = idx4 * 4;
        const int k = base >> 6, n = base & 63;
        uint32_t h01, h23;
        CVT_F16X2(h01, v.y, v.x);
        CVT_F16X2(h23, v.w, v.z);
        asm volatile("st.shared.v2.b32 [%0], {%1, %2};"
                     :: "r"(smB + (uint32_t)(k * B_STRIDE + n * 2)), "r"(h01), "r"(h23));
    }
    // cols 64..71: col64 = 1.0h (sum column), rest 0
    for (int k = tid; k < KANCH; k += 128)
        asm volatile("st.shared.v4.b32 [%0], {%1,%2,%2,%2};"
                     :: "r"(smB + (uint32_t)(k * B_STRIDE + 128)), "r"(0x00003C00u), "r"(0u));
    sAnch[tid]       = anchors_g[tid];
    sAnch[tid + 128] = anchors_g[tid + 128];
    __syncthreads();

    // ---- per-thread constants ----
    const float g    = fabsf(gamma_g[0]);
    const float l2e  = 1.4426950408889634f;
    const float c1   = -g * l2e;
    const float A0   = sAnch[0];
    const float dlt  = sAnch[1] - sAnch[0];
    const float rdlt = 1.0f / dlt;
    const float gd2l = g * dlt * dlt * l2e;
    const float m1   = 32.0f * g * dlt * l2e;
    const float m2   = -256.0f * gd2l;
    const float U1   = ex2f(-32.0f * gd2l);
    const float U8   = ex2f(-256.0f * gd2l);
    const float U9   = U8 * U1;
    const float Q    = ex2f(-512.0f * gd2l);

    const uint32_t bLane16 = smB + (uint32_t)(lane & 15) * B_STRIDE;
    const uint32_t bLane   = bLane16 + (uint32_t)(lane >> 4) * 16u;

    for (int tile = blockIdx.x; tile < ntiles; tile += gridDim.x) {
        const int rBase = tile * 64 + warp * 16 + group;   // rank of j=0 row

        // ---- per-row setup + hoisted recurrence init (2 rows/thread) ----
        float xv[2], wi[2][4], w[2][4], T[2];
        int   s0r[2], rowOf[2];
        int   lo = 16, hi = 0;
        #pragma unroll
        for (int j = 0; j < 2; j++) {
            const int rk = rBase + j * 8;
            xv[j]    = g_sortedX[rk];
            rowOf[j] = g_sortedIdx[rk];
            const int i0 = anchor_bin(xv[j], A0, rdlt);
            s0r[j] = max(i0 - WRAD, 0) >> 4;
            const int se = (min(i0 + WRAD, KANCH - 1) >> 4) + 1;
            lo = min(lo, s0r[j]);
            hi = max(hi, se);

            const int kb0 = s0r[j] * 16 + q * 2;
            const float2 aA = *reinterpret_cast<const float2*>(sAnch + kb0);
            const float2 aB = *reinterpret_cast<const float2*>(sAnch + kb0 + 8);
            const float d0 = xv[j] - aA.x, d1 = xv[j] - aA.y;
            const float d8 = xv[j] - aB.x, d9 = xv[j] - aB.y;
            wi[j][0] = ex2f((c1 * d0) * d0);
            wi[j][1] = ex2f((c1 * d1) * d1);
            wi[j][2] = ex2f((c1 * d8) * d8);
            wi[j][3] = ex2f((c1 * d9) * d9);
            T[j]     = ex2f(m1 * d0 + m2);
            w[j][0] = 0.0f; w[j][1] = 0.0f; w[j][2] = 0.0f; w[j][3] = 0.0f;
        }
        // warp union of step ranges (globally sorted rows -> very tight)
        #pragma unroll
        for (int off = 16; off > 0; off >>= 1) {
            lo = min(lo, __shfl_xor_sync(0xffffffffu, lo, off));
            hi = max(hi, __shfl_xor_sync(0xffffffffu, hi, off));
        }

        float acc[9][4];
        #pragma unroll
        for (int nt = 0; nt < 9; nt++)
            #pragma unroll
            for (int c = 0; c < 4; c++) acc[nt][c] = 0.0f;

        for (int s = lo; s < hi; s++) {
            // ---- B fragments: 8 E-octets + sum octet ----
            const uint32_t bRow = (uint32_t)(16 * s) * B_STRIDE;
            uint32_t b[9][2];
            #pragma unroll
            for (int nt = 0; nt < 8; nt += 2)
                LDMATRIX_X4T(b[nt][0], b[nt][1], b[nt + 1][0], b[nt + 1][1],
                             bLane + bRow + (uint32_t)(nt * 16));
            LDMATRIX_X2T(b[8][0], b[8][1], bLane16 + bRow + 128u);

            // ---- weights: branch-free recurrence (FSEL inject) ----
            #pragma unroll
            for (int j = 0; j < 2; j++) {
                const bool isInit  = (s == s0r[j]);
                const bool isAfter = (s > s0r[j]);
                const float f  = T[j];
                const float w0 = w[j][0] * f;
                const float w1 = w[j][1] * (f * U1);
                const float w2 = w[j][2] * (f * U8);
                const float w3 = w[j][3] * (f * U9);
                w[j][0] = isInit ? wi[j][0] : w0;
                w[j][1] = isInit ? wi[j][1] : w1;
                w[j][2] = isInit ? wi[j][2] : w2;
                w[j][3] = isInit ? wi[j][3] : w3;
                T[j]    = isAfter ? f * Q : f;
            }

            // ---- pack A fragment ----
            uint32_t afr[4];
            CVT_F16X2(afr[0], w[0][1], w[0][0]);
            CVT_F16X2(afr[1], w[1][1], w[1][0]);
            CVT_F16X2(afr[2], w[0][3], w[0][2]);
            CVT_F16X2(afr[3], w[1][3], w[1][2]);

            #pragma unroll
            for (int nt = 0; nt < 9; nt++)
                MMA16816(acc[nt], afr, b[nt]);
        }

        // ---- row inverse-sums from sum column (col 64 lives at q==0, c0/c2) ----
        const int srcLane = lane & ~3;
        const float iv0 = __shfl_sync(0xffffffffu, 1.0f / acc[8][0], srcLane);  // row group
        const float iv1 = __shfl_sync(0xffffffffu, 1.0f / acc[8][2], srcLane);  // row group+8

        // ---- epilogue: write through the global row permutation ----
        float* oLo = out_g + (size_t)rowOf[0] * EDIM + q * 2;
        float* oHi = out_g + (size_t)rowOf[1] * EDIM + q * 2;
        #pragma unroll
        for (int nt = 0; nt < 8; nt++) {
            float2 v0, v1;
            v0.x = acc[nt][0] * iv0;  v0.y = acc[nt][1] * iv0;
            v1.x = acc[nt][2] * iv1;  v1.y = acc[nt][3] * iv1;
            *reinterpret_cast<float2*>(oLo + nt * 8) = v0;
            *reinterpret_cast<float2*>(oHi + nt * 8) = v1;
        }
    }
}

extern "C" void kernel_launch(void* const* d_in, const int* in_sizes, int n_in,
                              void* d_out, int out_size) {
    const float* x       = (const float*)d_in[0];
    const float* anchors = (const float*)d_in[1];
    const float* emb     = (const float*)d_in[2];
    const float* gamma   = (const float*)d_in[3];
    float* out = (float*)d_out;

    const int rows   = in_sizes[0];          // 262144
    const int ntiles = rows / 64;            // 4096 tiles of 64 rows

    int dev = 0, nsm = 148;
    cudaGetDevice(&dev);
    cudaDeviceGetAttribute(&nsm, cudaDevAttrMultiProcessorCount, dev);
    int grid = 4 * nsm;                      // persistent: 4 CTAs per SM
    if (grid > ntiles) grid = ntiles;

    const int sgrid = (rows + SBLK - 1) / SBLK;   // 256 blocks

    k_hist<<<sgrid, SBLK>>>(x, anchors, rows, sgrid);
    k_scan<<<1, KANCH>>>(sgrid);
    k_scatter<<<sgrid, SBLK>>>(x, anchors, rows, sgrid);
    softquant_kernel<<<grid, 128>>>(anchors, emb, gamma, out, ntiles);
}

// round 13
// speedup vs baseline: 4.5854x; 4.5854x over previous
#include <cuda_runtime.h>
#include <cuda_fp16.h>
#include <cstdint>

// ============================================================================
// Soft-quantization codebook kernel — ldmatrix + mma.sync HMMA path.
//
// R12 -> R13:
//   * k_scan was a serial dependent-load loop (~140us!) -> parallel two-level
//     scan: k_scan_blk (one block per bin, smem Hillis-Steele) + k_scan_bin
//   * main kernel back to M=32 warp tiles (R10 fragment layout) on the global
//     sort: halves B ldmatrix traffic per row (L1 was 61% at M=16)
//   * sum-column B fragment is constant (col64=1.0) -> x2.trans deleted
// ============================================================================

#define ROWSMAX  262144
#define KANCH    256
#define EDIM     64
#define B_STRIDE 144                // bytes per B k-row (64 f16 + pad)
#define WRAD     32                 // window radius in anchors
#define SBLK     1024               // sort block size
#define NBLKMAX  512

__device__ int   g_cnt[KANCH * NBLKMAX];
__device__ int   g_ofs[KANCH * NBLKMAX];
__device__ int   g_binTot[KANCH];
__device__ int   g_binBase[KANCH];
__device__ float g_sortedX[ROWSMAX];
__device__ int   g_sortedIdx[ROWSMAX];

__device__ __forceinline__ uint32_t smem_u32(const void* p) {
    uint32_t a;
    asm("{ .reg .u64 t; cvta.to.shared.u64 t, %1; cvt.u32.u64 %0, t; }" : "=r"(a) : "l"(p));
    return a;
}

__device__ __forceinline__ float ex2f(float x) {
    float r;
    asm("ex2.approx.ftz.f32 %0, %1;" : "=f"(r) : "f"(x));
    return r;
}

__device__ __forceinline__ int anchor_bin(float xv, float A0, float rdlt) {
    int i0 = __float2int_rn((xv - A0) * rdlt);
    return min(max(i0, 0), KANCH - 1);
}

#define LDMATRIX_X4T(r0, r1, r2, r3, addr)                                        \
    asm volatile("ldmatrix.sync.aligned.m8n8.x4.trans.shared.b16 {%0,%1,%2,%3}, [%4];" \
        : "=r"(r0), "=r"(r1), "=r"(r2), "=r"(r3) : "r"(addr))

#define MMA16816(c, a, b0, b1)                                                    \
    asm volatile("mma.sync.aligned.m16n8k16.row.col.f32.f16.f16.f32 "             \
        "{%0,%1,%2,%3}, {%4,%5,%6,%7}, {%8,%9}, {%0,%1,%2,%3};"                   \
        : "+f"((c)[0]), "+f"((c)[1]), "+f"((c)[2]), "+f"((c)[3])                  \
        : "r"((a)[0]), "r"((a)[1]), "r"((a)[2]), "r"((a)[3]),                     \
          "r"(b0), "r"(b1))

#define CVT_F16X2(d, hi, lo) \
    asm("cvt.rn.f16x2.f32 %0, %1, %2;" : "=r"(d) : "f"(hi), "f"(lo))

// ---------------- sort pipeline (contention-free, parallel scan) ----------------

__global__ void __launch_bounds__(SBLK)
k_hist(const float* __restrict__ xg, const float* __restrict__ anchors_g,
       int n, int nblk) {
    __shared__ int sh[KANCH];
    const int tid = threadIdx.x;
    if (tid < KANCH) sh[tid] = 0;
    __syncthreads();
    const int i = blockIdx.x * SBLK + tid;
    const float A0 = anchors_g[0];
    const float rdlt = 1.0f / (anchors_g[1] - anchors_g[0]);
    if (i < n) atomicAdd(&sh[anchor_bin(xg[i], A0, rdlt)], 1);
    __syncthreads();
    if (tid < KANCH) g_cnt[tid * nblk + blockIdx.x] = sh[tid];   // plain store
}

// one block per bin: parallel exclusive scan over that bin's per-block counts
__global__ void __launch_bounds__(256)
k_scan_blk(int nblk) {
    __shared__ int sh[256];
    const int bin = blockIdx.x;
    const int t = threadIdx.x;
    const int v = (t < nblk) ? g_cnt[bin * nblk + t] : 0;
    sh[t] = v;
    __syncthreads();
    int run = v;
    #pragma unroll
    for (int off = 1; off < 256; off <<= 1) {
        const int u = (t >= off) ? sh[t - off] : 0;
        __syncthreads();
        sh[t] = run = run + u;
        __syncthreads();
    }
    if (t < nblk) g_ofs[bin * nblk + t] = run - v;   // exclusive within bin
    if (t == 255) g_binTot[bin] = run;               // bin total
}

// single block: exclusive scan of bin totals
__global__ void __launch_bounds__(KANCH)
k_scan_bin() {
    __shared__ int sh[KANCH];
    const int t = threadIdx.x;
    const int v = g_binTot[t];
    sh[t] = v;
    __syncthreads();
    int run = v;
    #pragma unroll
    for (int off = 1; off < KANCH; off <<= 1) {
        const int u = (t >= off) ? sh[t - off] : 0;
        __syncthreads();
        sh[t] = run = run + u;
        __syncthreads();
    }
    g_binBase[t] = run - v;
}

__global__ void __launch_bounds__(SBLK)
k_scatter(const float* __restrict__ xg, const float* __restrict__ anchors_g,
          int n, int nblk) {
    __shared__ int sh[KANCH];
    const int tid = threadIdx.x;
    if (tid < KANCH) sh[tid] = 0;
    __syncthreads();
    const int i = blockIdx.x * SBLK + tid;
    if (i >= n) return;
    const float A0 = anchors_g[0];
    const float rdlt = 1.0f / (anchors_g[1] - anchors_g[0]);
    const float xv = xg[i];
    const int bin = anchor_bin(xv, A0, rdlt);
    const int localOff = atomicAdd(&sh[bin], 1);     // smem-local, low contention
    const int pos = g_binBase[bin] + g_ofs[bin * nblk + blockIdx.x] + localOff;
    g_sortedX[pos]   = xv;
    g_sortedIdx[pos] = i;
}

// ---------------- main kernel: M=32 warp tiles on globally sorted rows ----------------

__global__ void __launch_bounds__(128, 3)
softquant_kernel(const float* __restrict__ anchors_g,
                 const float* __restrict__ emb_g,
                 const float* __restrict__ gamma_g,
                 float* __restrict__ out_g,
                 int ntiles)                      // tiles of 128 rows
{
    __shared__ __align__(128) unsigned char sBmem[KANCH * B_STRIDE];  // 36864 B
    __shared__ float sAnch[KANCH];

    const uint32_t smB = smem_u32(sBmem);

    const int tid   = threadIdx.x;
    const int lane  = tid & 31;
    const int warp  = tid >> 5;
    const int group = lane >> 2;     // 0..7
    const int q     = lane & 3;      // k-slot quad index

    // ---- one-time per CTA: E f32 -> f16 smem B cols 0..63 ----
    #pragma unroll
    for (int i = 0; i < 32; i++) {
        const int idx4 = tid + i * 128;
        const float4 v = reinterpret_cast<const float4*>(emb_g)[idx4];
        const int base = idx4 * 4;
        const int k = base >> 6, n = base & 63;
        uint32_t h01, h23;
        CVT_F16X2(h01, v.y, v.x);
        CVT_F16X2(h23, v.w, v.z);
        asm volatile("st.shared.v2.b32 [%0], {%1, %2};"
                     :: "r"(smB + (uint32_t)(k * B_STRIDE + n * 2)), "r"(h01), "r"(h23));
    }
    sAnch[tid]       = anchors_g[tid];
    sAnch[tid + 128] = anchors_g[tid + 128];
    __syncthreads();

    // ---- per-thread constants ----
    const float g    = fabsf(gamma_g[0]);
    const float l2e  = 1.4426950408889634f;
    const float c1   = -g * l2e;
    const float A0   = sAnch[0];
    const float dlt  = sAnch[1] - sAnch[0];
    const float rdlt = 1.0f / dlt;
    const float gd2l = g * dlt * dlt * l2e;
    const float m1   = 32.0f * g * dlt * l2e;
    const float m2   = -256.0f * gd2l;
    const float U1   = ex2f(-32.0f * gd2l);
    const float U8   = ex2f(-256.0f * gd2l);
    const float U9   = U8 * U1;
    const float Q    = ex2f(-512.0f * gd2l);

    // sum-column B fragment: col 64 = 1.0 for every k -> constant regs
    const uint32_t bSum = (group == 0) ? 0x3C003C00u : 0u;

    const uint32_t bLane = smB + (uint32_t)(lane & 15) * B_STRIDE + (uint32_t)(lane >> 4) * 16u;

    for (int tile = blockIdx.x; tile < ntiles; tile += gridDim.x) {
        const int rBase = tile * 128 + warp * 32 + group;

        // ---- per-row setup + hoisted recurrence init (4 rows/thread) ----
        float xv[4], wi[4][4], w[4][4], T[4];
        int   s0r[4], rowOf[4];
        int   lo = 16, hi = 0;
        #pragma unroll
        for (int j = 0; j < 4; j++) {
            const int rk = rBase + ((j >> 1) << 4) + ((j & 1) << 3);
            xv[j]    = g_sortedX[rk];
            rowOf[j] = g_sortedIdx[rk];
            const int i0 = anchor_bin(xv[j], A0, rdlt);
            s0r[j] = max(i0 - WRAD, 0) >> 4;
            const int se = (min(i0 + WRAD, KANCH - 1) >> 4) + 1;
            lo = min(lo, s0r[j]);
            hi = max(hi, se);

            const int kb0 = s0r[j] * 16 + q * 2;
            const float2 aA = *reinterpret_cast<const float2*>(sAnch + kb0);
            const float2 aB = *reinterpret_cast<const float2*>(sAnch + kb0 + 8);
            const float d0 = xv[j] - aA.x, d1 = xv[j] - aA.y;
            const float d8 = xv[j] - aB.x, d9 = xv[j] - aB.y;
            wi[j][0] = ex2f((c1 * d0) * d0);
            wi[j][1] = ex2f((c1 * d1) * d1);
            wi[j][2] = ex2f((c1 * d8) * d8);
            wi[j][3] = ex2f((c1 * d9) * d9);
            T[j]     = ex2f(m1 * d0 + m2);
            w[j][0] = 0.0f; w[j][1] = 0.0f; w[j][2] = 0.0f; w[j][3] = 0.0f;
        }
        // warp union of step ranges (globally sorted rows -> very tight)
        #pragma unroll
        for (int off = 16; off > 0; off >>= 1) {
            lo = min(lo, __shfl_xor_sync(0xffffffffu, lo, off));
            hi = max(hi, __shfl_xor_sync(0xffffffffu, hi, off));
        }

        float acc[2][9][4];
        #pragma unroll
        for (int mt = 0; mt < 2; mt++)
            #pragma unroll
            for (int nt = 0; nt < 9; nt++)
                #pragma unroll
                for (int c = 0; c < 4; c++) acc[mt][nt][c] = 0.0f;

        for (int s = lo; s < hi; s++) {
            // ---- B fragments: 8 E-octets (shared by both row halves) ----
            const uint32_t bRow = bLane + (uint32_t)(16 * s) * B_STRIDE;
            uint32_t b[8][2];
            #pragma unroll
            for (int nt = 0; nt < 8; nt += 2)
                LDMATRIX_X4T(b[nt][0], b[nt][1], b[nt + 1][0], b[nt + 1][1],
                             bRow + (uint32_t)(nt * 16));

            // ---- weights: branch-free recurrence (FSEL inject) ----
            #pragma unroll
            for (int j = 0; j < 4; j++) {
                const bool isInit  = (s == s0r[j]);
                const bool isAfter = (s > s0r[j]);
                const float f  = T[j];
                const float w0 = w[j][0] * f;
                const float w1 = w[j][1] * (f * U1);
                const float w2 = w[j][2] * (f * U8);
                const float w3 = w[j][3] * (f * U9);
                w[j][0] = isInit ? wi[j][0] : w0;
                w[j][1] = isInit ? wi[j][1] : w1;
                w[j][2] = isInit ? wi[j][2] : w2;
                w[j][3] = isInit ? wi[j][3] : w3;
                T[j]    = isAfter ? f * Q : f;
            }

            // ---- pack A fragments ----
            uint32_t afr[2][4];
            #pragma unroll
            for (int mt = 0; mt < 2; mt++) {
                const int j0 = mt * 2, j1 = mt * 2 + 1;
                CVT_F16X2(afr[mt][0], w[j0][1], w[j0][0]);
                CVT_F16X2(afr[mt][1], w[j1][1], w[j1][0]);
                CVT_F16X2(afr[mt][2], w[j0][3], w[j0][2]);
                CVT_F16X2(afr[mt][3], w[j1][3], w[j1][2]);
            }

            #pragma unroll
            for (int nt = 0; nt < 8; nt++) {
                MMA16816(acc[0][nt], afr[0], b[nt][0], b[nt][1]);
                MMA16816(acc[1][nt], afr[1], b[nt][0], b[nt][1]);
            }
            MMA16816(acc[0][8], afr[0], bSum, bSum);
            MMA16816(acc[1][8], afr[1], bSum, bSum);
        }

        // ---- row inverse-sums from sum column (col 64: q==0, c0/c2) ----
        const int srcLane = lane & ~3;
        float iv[4];
        iv[0] = __shfl_sync(0xffffffffu, 1.0f / acc[0][8][0], srcLane);  // row group
        iv[1] = __shfl_sync(0xffffffffu, 1.0f / acc[0][8][2], srcLane);  // +8
        iv[2] = __shfl_sync(0xffffffffu, 1.0f / acc[1][8][0], srcLane);  // +16
        iv[3] = __shfl_sync(0xffffffffu, 1.0f / acc[1][8][2], srcLane);  // +24

        // ---- epilogue: write through the global row permutation ----
        #pragma unroll
        for (int mt = 0; mt < 2; mt++) {
            const float iv0 = iv[mt * 2 + 0];
            const float iv1 = iv[mt * 2 + 1];
            float* oLo = out_g + (size_t)rowOf[mt * 2 + 0] * EDIM + q * 2;
            float* oHi = out_g + (size_t)rowOf[mt * 2 + 1] * EDIM + q * 2;
            #pragma unroll
            for (int nt = 0; nt < 8; nt++) {
                float2 v0, v1;
                v0.x = acc[mt][nt][0] * iv0;  v0.y = acc[mt][nt][1] * iv0;
                v1.x = acc[mt][nt][2] * iv1;  v1.y = acc[mt][nt][3] * iv1;
                *reinterpret_cast<float2*>(oLo + nt * 8) = v0;
                *reinterpret_cast<float2*>(oHi + nt * 8) = v1;
            }
        }
    }
}

extern "C" void kernel_launch(void* const* d_in, const int* in_sizes, int n_in,
                              void* d_out, int out_size) {
    const float* x       = (const float*)d_in[0];
    const float* anchors = (const float*)d_in[1];
    const float* emb     = (const float*)d_in[2];
    const float* gamma   = (const float*)d_in[3];
    float* out = (float*)d_out;

    const int rows   = in_sizes[0];          // 262144
    const int ntiles = rows / 128;           // 2048 tiles of 128 rows

    int dev = 0, nsm = 148;
    cudaGetDevice(&dev);
    cudaDeviceGetAttribute(&nsm, cudaDevAttrMultiProcessorCount, dev);
    int grid = 3 * nsm;                      // persistent: 3 CTAs per SM
    if (grid > ntiles) grid = ntiles;

    const int sgrid = (rows + SBLK - 1) / SBLK;   // 256 blocks

    k_hist<<<sgrid, SBLK>>>(x, anchors, rows, sgrid);
    k_scan_blk<<<KANCH, 256>>>(sgrid);
    k_scan_bin<<<1, KANCH>>>();
    k_scatter<<<sgrid, SBLK>>>(x, anchors, rows, sgrid);
    softquant_kernel<<<grid, 128>>>(anchors, emb, gamma, out, ntiles);
}